// round 8
// baseline (speedup 1.0000x reference)
#include <cuda_runtime.h>

#define NCTA 128
#define NTHR 512
#define SW   2052                      // W row stride (floats)
#define SA   132                       // A row stride (floats)
#define ABUF (64 * SA)
#define A_OFF (16 * SW)
#define BIAS_OFF (A_OFF + 2 * ABUF)
#define SMEM_FLOATS (BIAS_OFF + 16)    // 49744 floats = 198976 B
#define HNOFF (512 * 64 * 1024)

__device__ float g_h1[2][64 * 1024];
__device__ float g_h2[2][64 * 1024];
__device__ unsigned g_cnt, g_gen;

__device__ __forceinline__ unsigned su32(const void* p) {
    return (unsigned)__cvta_generic_to_shared(p);
}
#define CP16(d, s) asm volatile("cp.async.cg.shared.global [%0],[%1],16;" :: "r"(d), "l"(s))
#define CPCOMMIT() asm volatile("cp.async.commit_group;")
#define FMA2(c, a, b) asm("fma.rn.f32x2 %0,%1,%2,%0;" : "+l"(c) : "l"(a), "l"(b))
#define LDS2U64(lo, hi, ad) \
    asm volatile("ld.shared.v2.u64 {%0,%1},[%2];" : "=l"(lo), "=l"(hi) : "r"(ad))

union UF { unsigned long long u; float2 f; };

__device__ __forceinline__ float fast_tanh(float v) {
    float e = __expf(2.0f * v);
    return 1.0f - __fdividef(2.0f, e + 1.0f);
}

__device__ __forceinline__ void gsync() {
    __syncthreads();
    if (threadIdx.x == 0) {
        __threadfence();
        volatile unsigned* vg = &g_gen;
        volatile unsigned* vc = &g_cnt;
        unsigned g = *vg;
        if (atomicAdd(&g_cnt, 1u) == NCTA - 1) {
            *vc = 0u;
            __threadfence();
            *vg = g + 1u;
        } else {
            while (*vg == g) {}
            __threadfence();
        }
    }
    __syncthreads();
}

// stage one [64 m][128 k] activation chunk into A buffer `buf` via cp.async
__device__ __forceinline__ void stage(float* sm, int buf, const float* inp,
                                      const float* hp, int c) {
    const float* base = (c < 8) ? inp + c * 128 : hp + (c - 8) * 128;
    unsigned d0 = su32(sm) + (unsigned)(A_OFF + buf * ABUF) * 4u;
    int tid = threadIdx.x;
#pragma unroll
    for (int r = 0; r < 4; r++) {
        int idx = r * NTHR + tid;          // 2048 16B ops per chunk
        int m = idx >> 5, q = idx & 31;
        CP16(d0 + (unsigned)(m * SA + q * 4) * 4u, base + (size_t)m * 1024 + q * 4);
    }
    CPCOMMIT();
}

__global__ void rnn_init(const float* __restrict__ h0) {
    int i = blockIdx.x * blockDim.x + threadIdx.x;
    const int n = 64 * 1024;
    for (int idx = i; idx < n; idx += gridDim.x * blockDim.x) {
        g_h1[1][idx] = h0[idx];         // h1[t=-1] in buf 1
        g_h2[1][idx] = h0[n + idx];     // h2[t=-1] in buf 1
    }
    if (i == 0) { g_cnt = 0u; g_gen = 0u; }
}

__global__ void __launch_bounds__(NTHR, 1) rnn_main(
    const float* __restrict__ x,
    const float* __restrict__ Wx, const float* __restrict__ bx,
    const float* __restrict__ Wh, const float* __restrict__ bh,
    float* __restrict__ out, int out_size)
{
    extern __shared__ float sm[];
    const int tid = threadIdx.x, cta = blockIdx.x;
    const int layer = cta >> 6, col0 = (cta & 63) * 16;

    // ---- load fused [16 j][2048 k] weight slice into SMEM once ----
    {
        const float* wxl = Wx + (size_t)layer * 1024 * 1024;
        const float* whl = Wh + (size_t)layer * 1024 * 1024;
        unsigned wb = su32(sm);
#pragma unroll 4
        for (int r = 0; r < 16; r++) {
            int idx = r * NTHR + tid;      // 8192 16B ops
            int j = idx >> 9;
            int k4 = (idx & 511) * 4;
            const float* src = (k4 < 1024)
                ? wxl + (size_t)(col0 + j) * 1024 + k4
                : whl + (size_t)(col0 + j) * 1024 + (k4 - 1024);
            CP16(wb + (unsigned)(j * SW + k4) * 4u, src);
        }
        CPCOMMIT();
        if (tid < 16)
            sm[BIAS_OFF + tid] = bx[layer * 1024 + col0 + tid]
                               + bh[layer * 1024 + col0 + tid];
        asm volatile("cp.async.wait_group 0;");
        __syncthreads();
    }

    // 16 warps: wid = half(m) + 2*ks(k-slice of 16 within each 128-chunk)
    const int wid = tid >> 5, lane = tid & 31;
    const int half = wid & 1, ks = wid >> 1;     // half: 0..1, ks: 0..7
    const int mg = lane >> 2, jq = lane & 3;     // mg: 0..7, jq: 0..3
    const bool wr_hn = out_size >= HNOFF + 2 * 64 * 1024;
    const unsigned abase0 = su32(sm) + (unsigned)A_OFF * 4u
                          + (unsigned)((half * 32 + mg) * SA + ks * 16) * 4u;
    const unsigned wbase = su32(sm) + (unsigned)(jq * SW + ks * 16) * 4u;

    for (int p = 0; p <= 512; p++) {
        const bool act = (layer == 0) ? (p < 512) : (p >= 1);
        if (act) {
            const int t = (layer == 0) ? p : p - 1;
            const float* inp = (layer == 0) ? x + (size_t)t * 65536 : g_h1[t & 1];
            const float* hp  = (layer == 0) ? g_h1[(p + 1) & 1] : g_h2[(t + 1) & 1];
            float* hout      = (layer == 0) ? g_h1[p & 1] : g_h2[t & 1];

            unsigned long long acc[4][4];
#pragma unroll
            for (int i = 0; i < 4; i++)
#pragma unroll
                for (int jj = 0; jj < 4; jj++) acc[i][jj] = 0ull;

            stage(sm, 0, inp, hp, 0);

            for (int c = 0; c < 16; c++) {
                if (c < 15) {
                    stage(sm, (c + 1) & 1, inp, hp, c + 1);
                    asm volatile("cp.async.wait_group 1;");
                } else {
                    asm volatile("cp.async.wait_group 0;");
                }
                __syncthreads();
                const unsigned ab  = abase0 + (unsigned)((c & 1) * ABUF) * 4u;
                const unsigned wbc = wbase + (unsigned)(c * 128) * 4u;
#pragma unroll
                for (int s = 0; s < 4; s++) {          // 4 k each
                    unsigned long long a[4][2], w[4][2];
#pragma unroll
                    for (int i = 0; i < 4; i++)
                        LDS2U64(a[i][0], a[i][1], ab + s * 16 + i * (8 * SA * 4));
#pragma unroll
                    for (int jj = 0; jj < 4; jj++)
                        LDS2U64(w[jj][0], w[jj][1], wbc + s * 16 + jj * (4 * SW * 4));
#pragma unroll
                    for (int i = 0; i < 4; i++)
#pragma unroll
                        for (int jj = 0; jj < 4; jj++) {
                            FMA2(acc[i][jj], a[i][0], w[jj][0]);
                            FMA2(acc[i][jj], a[i][1], w[jj][1]);
                        }
                }
                __syncthreads();
            }

            // ---- cross-warp K reduction: red[ks][m 64][j 16] (reuse A region) ----
            float* red = sm + A_OFF;
#pragma unroll
            for (int i = 0; i < 4; i++)
#pragma unroll
                for (int jj = 0; jj < 4; jj++) {
                    UF u; u.u = acc[i][jj];
                    red[ks * 1024 + (half * 32 + mg + 8 * i) * 16 + (jq + 4 * jj)]
                        = u.f.x + u.f.y;
                }
            __syncthreads();
            {
                // each thread: 2 outputs (m, jc..jc+1)
                const int m = tid >> 3, jc = (tid & 7) * 2;
                float2 s2 = make_float2(0.f, 0.f);
#pragma unroll
                for (int k8 = 0; k8 < 8; k8++) {
                    float2 v = *(const float2*)&red[k8 * 1024 + m * 16 + jc];
                    s2.x += v.x; s2.y += v.y;
                }
                float2 b2 = *(const float2*)&sm[BIAS_OFF + jc];
                float2 h2;
                h2.x = fast_tanh(s2.x + b2.x);
                h2.y = fast_tanh(s2.y + b2.y);
                *(float2*)&hout[m * 1024 + col0 + jc] = h2;
                if (layer == 1) {
                    float2 o2 = make_float2(10.f * h2.x, 10.f * h2.y);
                    *(float2*)&out[(size_t)t * 65536 + m * 1024 + col0 + jc] = o2;
                }
                if (wr_hn && t == 511)
                    *(float2*)&out[HNOFF + (size_t)layer * 65536
                                   + m * 1024 + col0 + jc] = h2;
            }
        }
        gsync();
    }
}

extern "C" void kernel_launch(void* const* d_in, const int* in_sizes, int n_in,
                              void* d_out, int out_size) {
    const float* x  = (const float*)d_in[0];
    const float* h0 = (const float*)d_in[1];
    const float* Wx = (const float*)d_in[2];
    const float* bx = (const float*)d_in[3];
    const float* Wh = (const float*)d_in[4];
    const float* bh = (const float*)d_in[5];
    (void)in_sizes; (void)n_in;

    cudaFuncSetAttribute(rnn_main, cudaFuncAttributeMaxDynamicSharedMemorySize,
                         SMEM_FLOATS * 4);
    rnn_init<<<64, 256>>>(h0);
    rnn_main<<<NCTA, NTHR, SMEM_FLOATS * 4>>>(x, Wx, bx, Wh, bh,
                                              (float*)d_out, out_size);
}

// round 9
// speedup vs baseline: 1.2892x; 1.2892x over previous
#include <cuda_runtime.h>

#define NCTA 128
#define NTHR 512
#define SW   2052                        // W row stride (floats)
#define SAW  20                          // per-warp A row stride (floats)
#define AWBUF (32 * SAW)                 // 640 floats: one [32m x 16k] buffer
#define A_OFF (16 * SW)                  // 32832
#define BIAS_OFF (A_OFF + 16 * 2 * AWBUF)   // 53312
#define SMEM_FLOATS (BIAS_OFF + 16)      // 53328 floats = 213312 B
#define HNOFF (512 * 64 * 1024)

__device__ float g_h1[2][64 * 1024];
__device__ float g_h2[2][64 * 1024];
__device__ unsigned g_cnt, g_gen;

__device__ __forceinline__ unsigned su32(const void* p) {
    return (unsigned)__cvta_generic_to_shared(p);
}
#define CP16(d, s) asm volatile("cp.async.cg.shared.global [%0],[%1],16;" :: "r"(d), "l"(s))
#define CPCOMMIT() asm volatile("cp.async.commit_group;")
#define FMA2(c, a, b) asm("fma.rn.f32x2 %0,%1,%2,%0;" : "+l"(c) : "l"(a), "l"(b))
#define LDS2U64(lo, hi, ad) \
    asm volatile("ld.shared.v2.u64 {%0,%1},[%2];" : "=l"(lo), "=l"(hi) : "r"(ad))

union UF { unsigned long long u; float2 f; };

__device__ __forceinline__ float fast_tanh(float v) {
    float e = __expf(2.0f * v);
    return 1.0f - __fdividef(2.0f, e + 1.0f);
}

__device__ __forceinline__ void gsync() {
    __syncthreads();
    if (threadIdx.x == 0) {
        __threadfence();
        volatile unsigned* vg = &g_gen;
        volatile unsigned* vc = &g_cnt;
        unsigned g = *vg;
        if (atomicAdd(&g_cnt, 1u) == NCTA - 1) {
            *vc = 0u;
            __threadfence();
            *vg = g + 1u;
        } else {
            while (*vg == g) {}
            __threadfence();
        }
    }
    __syncthreads();
}

__global__ void rnn_init(const float* __restrict__ h0) {
    int i = blockIdx.x * blockDim.x + threadIdx.x;
    const int n = 64 * 1024;
    for (int idx = i; idx < n; idx += gridDim.x * blockDim.x) {
        g_h1[1][idx] = h0[idx];
        g_h2[1][idx] = h0[n + idx];
    }
    if (i == 0) { g_cnt = 0u; g_gen = 0u; }
}

__global__ void __launch_bounds__(NTHR, 1) rnn_main(
    const float* __restrict__ x,
    const float* __restrict__ Wx, const float* __restrict__ bx,
    const float* __restrict__ Wh, const float* __restrict__ bh,
    float* __restrict__ out, int out_size)
{
    extern __shared__ float sm[];
    const int tid = threadIdx.x, cta = blockIdx.x;
    const int layer = cta >> 6, col0 = (cta & 63) * 16;

    // ---- load fused [16 j][2048 k] weight slice into SMEM once ----
    {
        const float* wxl = Wx + (size_t)layer * 1024 * 1024;
        const float* whl = Wh + (size_t)layer * 1024 * 1024;
        unsigned wb = su32(sm);
#pragma unroll 4
        for (int r = 0; r < 16; r++) {
            int idx = r * NTHR + tid;
            int j = idx >> 9;
            int k4 = (idx & 511) * 4;
            const float* src = (k4 < 1024)
                ? wxl + (size_t)(col0 + j) * 1024 + k4
                : whl + (size_t)(col0 + j) * 1024 + (k4 - 1024);
            CP16(wb + (unsigned)(j * SW + k4) * 4u, src);
        }
        CPCOMMIT();
        if (tid < 16)
            sm[BIAS_OFF + tid] = bx[layer * 1024 + col0 + tid]
                               + bh[layer * 1024 + col0 + tid];
        asm volatile("cp.async.wait_group 0;");
        __syncthreads();
    }

    // 16 warps = 2 m-halves x 8 k-ranges (256 k each); no intra-phase CTA sync
    const int wid = tid >> 5, lane = tid & 31;
    const int half = wid & 1, ks = wid >> 1;      // half: m 32-row half, ks: k-range
    const int mg = lane >> 2, jq = lane & 3;
    const bool wr_hn = out_size >= HNOFF + 2 * 64 * 1024;
    const int kbase = ks * 256;
    const unsigned awarp = su32(sm) + (unsigned)(A_OFF + wid * 2 * AWBUF) * 4u;
    const unsigned wko = su32(sm) + (unsigned)(jq * SW + kbase) * 4u;
    float* red = sm + A_OFF;

    for (int p = 0; p <= 512; p++) {
        const bool act = (layer == 0) ? (p < 512) : (p >= 1);
        if (act) {
            const int t = (layer == 0) ? p : p - 1;
            const float* inp = (layer == 0) ? x + (size_t)t * 65536 : g_h1[t & 1];
            const float* hp  = (layer == 0) ? g_h1[(p + 1) & 1] : g_h2[(t + 1) & 1];
            float* hout      = (layer == 0) ? g_h1[p & 1] : g_h2[t & 1];
            // this warp's k-range source matrix (row-major [64][1024])
            const float* src = (kbase < 1024) ? inp + kbase : hp + (kbase - 1024);

            unsigned long long acc[4][4];
#pragma unroll
            for (int i = 0; i < 4; i++)
#pragma unroll
                for (int jj = 0; jj < 4; jj++) acc[i][jj] = 0ull;

            // stage sub-chunk 0 (this warp only): [32 m][16 k]
#pragma unroll
            for (int r = 0; r < 4; r++) {
                int idx = r * 32 + lane;
                int m = idx >> 2, q = idx & 3;
                CP16(awarp + (unsigned)(m * SAW + q * 4) * 4u,
                     src + (size_t)(half * 32 + m) * 1024 + q * 4);
            }
            CPCOMMIT();

            for (int sub = 0; sub < 16; sub++) {
                if (sub < 15) {
                    const float* s2 = src + (sub + 1) * 16;
                    unsigned d0 = awarp + (unsigned)(((sub + 1) & 1) * AWBUF) * 4u;
#pragma unroll
                    for (int r = 0; r < 4; r++) {
                        int idx = r * 32 + lane;
                        int m = idx >> 2, q = idx & 3;
                        CP16(d0 + (unsigned)(m * SAW + q * 4) * 4u,
                             s2 + (size_t)(half * 32 + m) * 1024 + q * 4);
                    }
                    CPCOMMIT();
                    asm volatile("cp.async.wait_group 1;");
                } else {
                    asm volatile("cp.async.wait_group 0;");
                }
                __syncwarp();
                const unsigned ab = awarp + (unsigned)((sub & 1) * AWBUF) * 4u
                                  + (unsigned)(mg * SAW) * 4u;
                const unsigned wb = wko + (unsigned)(sub * 16) * 4u;
#pragma unroll
                for (int s = 0; s < 4; s++) {          // 4 k each
                    unsigned long long w0[4], w1[4];
#pragma unroll
                    for (int jj = 0; jj < 4; jj++)
                        LDS2U64(w0[jj], w1[jj], wb + s * 16 + jj * (4 * SW * 4));
#pragma unroll
                    for (int i = 0; i < 4; i++) {
                        unsigned long long a0, a1;
                        LDS2U64(a0, a1, ab + s * 16 + i * (8 * SAW * 4));
#pragma unroll
                        for (int jj = 0; jj < 4; jj++) {
                            FMA2(acc[i][jj], a0, w0[jj]);
                            FMA2(acc[i][jj], a1, w1[jj]);
                        }
                    }
                }
                __syncwarp();
            }

            // ---- cross-warp K reduction: red[ks][64 m][16 j] (aliases A bufs) ----
            __syncthreads();
#pragma unroll
            for (int i = 0; i < 4; i++)
#pragma unroll
                for (int jj = 0; jj < 4; jj++) {
                    UF u; u.u = acc[i][jj];
                    red[ks * 1024 + (half * 32 + mg + 8 * i) * 16 + (jq + 4 * jj)]
                        = u.f.x + u.f.y;
                }
            __syncthreads();
            {
                const int m = tid >> 3, jc = (tid & 7) * 2;
                float2 s2 = make_float2(0.f, 0.f);
#pragma unroll
                for (int k8 = 0; k8 < 8; k8++) {
                    float2 v = *(const float2*)&red[k8 * 1024 + m * 16 + jc];
                    s2.x += v.x; s2.y += v.y;
                }
                float2 b2 = *(const float2*)&sm[BIAS_OFF + jc];
                float2 h2;
                h2.x = fast_tanh(s2.x + b2.x);
                h2.y = fast_tanh(s2.y + b2.y);
                *(float2*)&hout[m * 1024 + col0 + jc] = h2;
                if (layer == 1) {
                    float2 o2 = make_float2(10.f * h2.x, 10.f * h2.y);
                    *(float2*)&out[(size_t)t * 65536 + m * 1024 + col0 + jc] = o2;
                }
                if (wr_hn && t == 511)
                    *(float2*)&out[HNOFF + (size_t)layer * 65536
                                   + m * 1024 + col0 + jc] = h2;
            }
        }
        gsync();
    }
}

extern "C" void kernel_launch(void* const* d_in, const int* in_sizes, int n_in,
                              void* d_out, int out_size) {
    const float* x  = (const float*)d_in[0];
    const float* h0 = (const float*)d_in[1];
    const float* Wx = (const float*)d_in[2];
    const float* bx = (const float*)d_in[3];
    const float* Wh = (const float*)d_in[4];
    const float* bh = (const float*)d_in[5];
    (void)in_sizes; (void)n_in;

    cudaFuncSetAttribute(rnn_main, cudaFuncAttributeMaxDynamicSharedMemorySize,
                         SMEM_FLOATS * 4);
    rnn_init<<<64, 256>>>(h0);
    rnn_main<<<NCTA, NTHR, SMEM_FLOATS * 4>>>(x, Wx, bx, Wh, bh,
                                              (float*)d_out, out_size);
}

// round 10
// speedup vs baseline: 1.4751x; 1.1442x over previous
#include <cuda_runtime.h>

#define NCTA 128
#define NTHR 512
#define SW   2052                        // W row stride (floats)
#define SAW  20                          // per-warp A row stride (floats)
#define AWBUF (32 * SAW)                 // 640 floats: one [32m x 16k] buffer
#define A_OFF (16 * SW)                  // 32832
#define BIAS_OFF (A_OFF + 16 * 2 * AWBUF)   // 53312
#define SMEM_FLOATS (BIAS_OFF + 16)      // 213312 B
#define HNOFF (512 * 64 * 1024)

__device__ float g_h1[3][64 * 1024];     // layer-0 h, mod-3 (read distance 2)
__device__ float g_h2[2][64 * 1024];     // layer-1 h, mod-2
__device__ unsigned g_cnt, g_gen;

__device__ __forceinline__ unsigned su32(const void* p) {
    return (unsigned)__cvta_generic_to_shared(p);
}
#define CP16(d, s) asm volatile("cp.async.cg.shared.global [%0],[%1],16;" :: "r"(d), "l"(s))
#define CPCOMMIT() asm volatile("cp.async.commit_group;")
#define FMA2(c, a, b) asm("fma.rn.f32x2 %0,%1,%2,%0;" : "+l"(c) : "l"(a), "l"(b))
#define LDS2U64(lo, hi, ad) \
    asm volatile("ld.shared.v2.u64 {%0,%1},[%2];" : "=l"(lo), "=l"(hi) : "r"(ad))

union UF { unsigned long long u; float2 f; };

__device__ __forceinline__ unsigned ld_vol(const unsigned* p) {
    unsigned v;
    asm volatile("ld.volatile.global.u32 %0,[%1];" : "=r"(v) : "l"(p));
    return v;
}
__device__ __forceinline__ void st_vol(unsigned* p, unsigned v) {
    asm volatile("st.volatile.global.u32 [%0],%1;" :: "l"(p), "r"(v));
}

__device__ __forceinline__ float fast_tanh(float v) {
    float e = __expf(2.0f * v);
    return 1.0f - __fdividef(2.0f, e + 1.0f);
}

__global__ void rnn_init(const float* __restrict__ h0) {
    int i = blockIdx.x * blockDim.x + threadIdx.x;
    const int n = 64 * 1024;
    for (int idx = i; idx < n; idx += gridDim.x * blockDim.x) {
        g_h1[2][idx] = h0[idx];          // h1[t=-1] lives in slot 2
        g_h2[1][idx] = h0[n + idx];      // h2[t=-1] lives in slot 1
    }
    if (i == 0) { g_cnt = 0u; g_gen = 0u; }
}

__global__ void __launch_bounds__(NTHR, 1) rnn_main(
    const float* __restrict__ x,
    const float* __restrict__ Wx, const float* __restrict__ bx,
    const float* __restrict__ Wh, const float* __restrict__ bh,
    float* __restrict__ out, int out_size)
{
    extern __shared__ float sm[];
    const int tid = threadIdx.x, cta = blockIdx.x;
    const int layer = cta >> 6, col0 = (cta & 63) * 16;

    // ---- load fused [16 j][2048 k] weight slice into SMEM once ----
    {
        const float* wxl = Wx + (size_t)layer * 1024 * 1024;
        const float* whl = Wh + (size_t)layer * 1024 * 1024;
        unsigned wb = su32(sm);
#pragma unroll 4
        for (int r = 0; r < 16; r++) {
            int idx = r * NTHR + tid;
            int j = idx >> 9;
            int k4 = (idx & 511) * 4;
            const float* src = (k4 < 1024)
                ? wxl + (size_t)(col0 + j) * 1024 + k4
                : whl + (size_t)(col0 + j) * 1024 + (k4 - 1024);
            CP16(wb + (unsigned)(j * SW + k4) * 4u, src);
        }
        CPCOMMIT();
        if (tid < 16)
            sm[BIAS_OFF + tid] = bx[layer * 1024 + col0 + tid]
                               + bh[layer * 1024 + col0 + tid];
        asm volatile("cp.async.wait_group 0;");
        __syncthreads();
    }

    // 16 warps = 2 m-halves x 8 k-subranges (128 k per warp per half)
    const int wid = tid >> 5, lane = tid & 31;
    const int half = wid & 1, ks = wid >> 1;
    const int mg = lane >> 2, jq = lane & 3;
    const int kb = ks * 128;
    const bool wr_hn = out_size >= HNOFF + 2 * 64 * 1024;
    const unsigned awarp = su32(sm) + (unsigned)(A_OFF + wid * 2 * AWBUF) * 4u;
    const unsigned wbj = su32(sm) + (unsigned)(jq * SW) * 4u;
    float* red = sm + A_OFF;

    unsigned long long acc[4][4];

    // one half-GEMM (8 subs of 16 k) over src (row-major [64][1024], pre-offset
    // to this warp's k-range) against W smem columns starting at wkoff
    auto ghalf = [&](const float* src, int wkoff) {
        {   // stage sub 0
#pragma unroll
            for (int r = 0; r < 4; r++) {
                int idx = r * 32 + lane;
                int m = idx >> 2, q = idx & 3;
                CP16(awarp + (unsigned)(m * SAW + q * 4) * 4u,
                     src + (size_t)(half * 32 + m) * 1024 + q * 4);
            }
            CPCOMMIT();
        }
        for (int sub = 0; sub < 8; sub++) {
            if (sub < 7) {
                const float* s2 = src + (sub + 1) * 16;
                unsigned d0 = awarp + (unsigned)(((sub + 1) & 1) * AWBUF) * 4u;
#pragma unroll
                for (int r = 0; r < 4; r++) {
                    int idx = r * 32 + lane;
                    int m = idx >> 2, q = idx & 3;
                    CP16(d0 + (unsigned)(m * SAW + q * 4) * 4u,
                         s2 + (size_t)(half * 32 + m) * 1024 + q * 4);
                }
                CPCOMMIT();
                asm volatile("cp.async.wait_group 1;");
            } else {
                asm volatile("cp.async.wait_group 0;");
            }
            __syncwarp();
            const unsigned ab = awarp + (unsigned)((sub & 1) * AWBUF) * 4u
                              + (unsigned)(mg * SAW) * 4u;
            const unsigned wb = wbj + (unsigned)(wkoff + sub * 16) * 4u;
#pragma unroll
            for (int s = 0; s < 4; s++) {
                unsigned long long w0[4], w1[4];
#pragma unroll
                for (int jj = 0; jj < 4; jj++)
                    LDS2U64(w0[jj], w1[jj], wb + s * 16 + jj * (4 * SW * 4));
#pragma unroll
                for (int i = 0; i < 4; i++) {
                    unsigned long long a0, a1;
                    LDS2U64(a0, a1, ab + s * 16 + i * (8 * SAW * 4));
#pragma unroll
                    for (int jj = 0; jj < 4; jj++) {
                        FMA2(acc[i][jj], a0, w0[jj]);
                        FMA2(acc[i][jj], a1, w1[jj]);
                    }
                }
            }
            __syncwarp();
        }
    };

    for (int p = 0; p <= 513; p++) {
        const bool act = (layer == 0) ? (p < 512) : (p >= 2);
        if (act) {
            const int t = (layer == 0) ? p : p - 2;
            // inp half (k<1024): wait-free (x, or h1 published >=2 flips ago)
            const float* src_inp = (layer == 0) ? x + (size_t)t * 65536
                                                : g_h1[(p - 2) % 3];
            // rec half (k>=1024): own h from previous phase -> needs gen>=p
            const float* src_rec = (layer == 0) ? g_h1[(p + 2) % 3]
                                                : g_h2[(p + 1) & 1];
            float* hout = (layer == 0) ? g_h1[p % 3] : g_h2[p & 1];

#pragma unroll
            for (int i = 0; i < 4; i++)
#pragma unroll
                for (int jj = 0; jj < 4; jj++) acc[i][jj] = 0ull;

            ghalf(src_inp + kb, kb);                   // pre-flip work

            while (ld_vol(&g_gen) < (unsigned)p) {}    // per-warp spin
            __syncwarp();

            ghalf(src_rec + kb, 1024 + kb);            // post-flip work

            // ---- cross-warp K reduction: red[ks][64 m][16 j] ----
            __syncthreads();
#pragma unroll
            for (int i = 0; i < 4; i++)
#pragma unroll
                for (int jj = 0; jj < 4; jj++) {
                    UF u; u.u = acc[i][jj];
                    red[ks * 1024 + (half * 32 + mg + 8 * i) * 16 + (jq + 4 * jj)]
                        = u.f.x + u.f.y;
                }
            __syncthreads();
            {
                const int m = tid >> 3, jc = (tid & 7) * 2;
                float2 s2 = make_float2(0.f, 0.f);
#pragma unroll
                for (int k8 = 0; k8 < 8; k8++) {
                    float2 v = *(const float2*)&red[k8 * 1024 + m * 16 + jc];
                    s2.x += v.x; s2.y += v.y;
                }
                float2 b2 = *(const float2*)&sm[BIAS_OFF + jc];
                float2 h2;
                h2.x = fast_tanh(s2.x + b2.x);
                h2.y = fast_tanh(s2.y + b2.y);
                *(float2*)&hout[m * 1024 + col0 + jc] = h2;
                if (layer == 1) {
                    float2 o2 = make_float2(10.f * h2.x, 10.f * h2.y);
                    *(float2*)&out[(size_t)t * 65536 + m * 1024 + col0 + jc] = o2;
                }
                if (wr_hn && t == 511)
                    *(float2*)&out[HNOFF + (size_t)layer * 65536
                                   + m * 1024 + col0 + jc] = h2;
            }
        } else {
            // inactive edge phases: still observe gen>=p so arrivals don't mix
            while (ld_vol(&g_gen) < (unsigned)p) {}
        }
        __syncthreads();
        if (tid == 0) {
            __threadfence();
            if (atomicAdd(&g_cnt, 1u) == NCTA - 1u) {
                st_vol(&g_cnt, 0u);
                __threadfence();
                st_vol(&g_gen, (unsigned)p + 1u);
            }
        }
    }
}

extern "C" void kernel_launch(void* const* d_in, const int* in_sizes, int n_in,
                              void* d_out, int out_size) {
    const float* x  = (const float*)d_in[0];
    const float* h0 = (const float*)d_in[1];
    const float* Wx = (const float*)d_in[2];
    const float* bx = (const float*)d_in[3];
    const float* Wh = (const float*)d_in[4];
    const float* bh = (const float*)d_in[5];
    (void)in_sizes; (void)n_in;

    cudaFuncSetAttribute(rnn_main, cudaFuncAttributeMaxDynamicSharedMemorySize,
                         SMEM_FLOATS * 4);
    rnn_init<<<64, 256>>>(h0);
    rnn_main<<<NCTA, NTHR, SMEM_FLOATS * 4>>>(x, Wx, bx, Wh, bh,
                                              (float*)d_out, out_size);
}